// round 12
// baseline (speedup 1.0000x reference)
#include <cuda_runtime.h>

// RVOModule on GB300. B=256, N=1024, K=32.
// R12: 4 lanes per pedestrian (lane owns 8 neighbors = two int4 quads),
// 8 peds/pass, 4 passes -> 2-level shuffle reduction (was 3-level x pairing).
// Unconditional smem gathers (L1 has headroom; drops per-interaction FSETP).
// R11 slimmed math, idx/mask prefetch, smem-staged batch state.

#define TAU 3.0f
#define FIX 0.2f

#define NPED 1024
#define KNEI 32
#define BPB 2                 // blocks per batch
#define THREADS 512           // peds per block

__device__ __forceinline__ float rsqrt_approx(float x) {
    float r;
    asm("rsqrt.approx.f32 %0, %1;" : "=f"(r) : "f"(x));
    return r;
}

__device__ __forceinline__ void interact(const float4 sf, const float2 vd,
                                         const float4 qv, const float thr2m,
                                         float& cx, float& cy)
{
    const float rpx = sf.x - qv.x;
    const float rpy = sf.y - qv.y;
    const float rvx = vd.x - qv.z;
    const float rvy = vd.y - qv.w;

    const float dpv = fmaf(rpx, rvx, rpy * rvy);
    // ref: (sum + 1e-6) + 1e-6 == sum + 2e-6 (to <1 ulp)
    const float dvv = fmaf(rvx, rvx, fmaf(rvy, rvy, 2e-6f));
    float t = __fdividef(dpv, dvv);
    t = fminf(fmaxf(t, 0.0f), TAU);

    const float dx = fmaf(t, rvx, rpx);
    const float dy = fmaf(t, rvy, rpy);
    const float md2 = fmaf(dx, dx, dy * dy);      // min_dist^2
    const float s   = fmaf(rpx, rpx, rpy * rpy);  // |rel_pos|^2

    // thr2m = thr^2 * m (m in {0,1}): m==0 -> md2<0 never true -> contrib 0.
    // s==0 (self, m==1): rp==0 -> contrib 0 * finite = 0 (matches ref).
    const float inv = (md2 < thr2m) ? rsqrt_approx(fmaxf(s, 1e-30f)) : 0.0f;

    cx -= rpy * inv;
    cy += rpx * inv;
}

__global__ __launch_bounds__(THREADS, 2)
void rvo_kernel(const float2* __restrict__ p_cur,
                const float2* __restrict__ v_cur,
                const float2* __restrict__ v_desire,
                const int*    __restrict__ near_idx,
                const float*  __restrict__ neigh_mask,
                const int*    __restrict__ thr_ptr,
                float2*       __restrict__ out)
{
    __shared__ float4 pv[NPED];       // {p.x,p.y,v.x,v.y} whole batch, 16 KB
    __shared__ float2 vds[THREADS];   // v_desire for this block's peds, 4 KB

    const int b       = blockIdx.x / BPB;
    const int sub     = blockIdx.x % BPB;
    const int base    = b * NPED;
    const int pedbase = sub * THREADS;

    #pragma unroll
    for (int i = threadIdx.x; i < NPED; i += THREADS) {
        const float2 p = p_cur[base + i];
        const float2 v = v_cur[base + i];
        pv[i] = make_float4(p.x, p.y, v.x, v.y);
    }
    vds[threadIdx.x] = v_desire[base + pedbase + threadIdx.x];
    __syncthreads();

    const int warp = threadIdx.x >> 5;
    const int lane = threadIdx.x & 31;
    const int pip  = lane >> 2;            // ped in pass (0..7)
    const int qb   = (lane & 3) * 2;       // lane's first int4 quad (0,2,4,6)

    const float thrF = (float)(*thr_ptr);
    const float thr2 = thrF * thrF;

    const int nb = pedbase + warp * 32;    // within-batch id of warp's first ped
    const int g0 = base + nb;

    // 8 int4 per ped. Lane's fixed offset within a pass.
    const int laneoff = pip * (KNEI / 4) + qb;
    const int4*   idx4 = (const int4*)  (near_idx)   + (long long)g0 * (KNEI / 4) + laneoff;
    const float4* msk4 = (const float4*)(neigh_mask) + (long long)g0 * (KNEI / 4) + laneoff;

    // Prologue: pass 0 (two quads per lane).
    int4   j0 = idx4[0];        int4   j1 = idx4[1];
    float4 m0 = msk4[0];        float4 m1 = msk4[1];

    #pragma unroll 1
    for (int c = 0; c < 4; ++c) {
        // Prefetch next pass — overlaps with compute.
        int4 j0n, j1n; float4 m0n, m1n;
        if (c < 3) {
            j0n = idx4[(c + 1) * 64];  j1n = idx4[(c + 1) * 64 + 1];
            m0n = msk4[(c + 1) * 64];  m1n = msk4[(c + 1) * 64 + 1];
        }

        const int pl = c * 8 + pip;          // ped offset within warp's 32
        const float4 sf = pv[nb + pl];       // broadcast to 4 lanes
        const float2 vd = vds[warp * 32 + pl];

        float cx = 0.0f, cy = 0.0f;

        const int   js[8] = { j0.x, j0.y, j0.z, j0.w, j1.x, j1.y, j1.z, j1.w };
        const float ms[8] = { m0.x, m0.y, m0.z, m0.w, m1.x, m1.y, m1.z, m1.w };

        #pragma unroll
        for (int u = 0; u < 8; ++u) {
            const float4 qv = pv[js[u]];     // unconditional LDS.128 gather
            interact(sf, vd, qv, thr2 * ms[u], cx, cy);
        }

        // 2-level reduction across the 4 lanes sharing this pedestrian.
        #pragma unroll
        for (int o = 1; o < 4; o <<= 1) {
            cx += __shfl_xor_sync(0xffffffffu, cx, o);
            cy += __shfl_xor_sync(0xffffffffu, cy, o);
        }

        if ((lane & 3) == 0) {
            out[g0 + pl] = make_float2(vd.x + cx * FIX, vd.y + cy * FIX);
        }

        j0 = j0n; j1 = j1n; m0 = m0n; m1 = m1n;
    }
}

extern "C" void kernel_launch(void* const* d_in, const int* in_sizes, int n_in,
                              void* d_out, int out_size)
{
    const float2* p_cur    = (const float2*)d_in[0];
    const float2* v_cur    = (const float2*)d_in[1];
    const float2* v_desire = (const float2*)d_in[2];
    const int*    near_idx = (const int*)d_in[3];
    const float*  mask     = (const float*)d_in[4];
    const int*    thr      = (const int*)d_in[5];
    float2*       out      = (float2*)d_out;

    const int P = in_sizes[0] / 2;          // B*N pedestrians
    const int nBatches = P / NPED;          // 256
    const int blocks = nBatches * BPB;      // 512

    rvo_kernel<<<blocks, THREADS>>>(p_cur, v_cur, v_desire, near_idx, mask, thr, out);
}

// round 13
// speedup vs baseline: 1.1009x; 1.1009x over previous
#include <cuda_runtime.h>

// RVOModule on GB300. B=256, N=1024, K=32.
// R13 = R11 memory structure (warp owns 32 peds, 8 passes x 4 peds x 8 lanes,
// coalesced prefetched int4/float4 idx+mask, predicated LDS.128 gathers,
// smem-staged batch state) + packed f32x2 math over neighbor PAIRS
// (sub/mul/fma.rn.f32x2 via PTX; bitwise-identical to scalar fma.rn).

#define TAU 3.0f
#define FIX 0.2f

#define NPED 1024
#define KNEI 32
#define BPB 2                 // blocks per batch
#define THREADS 512           // peds per block

typedef unsigned long long f32x2;

__device__ __forceinline__ f32x2 pk(float lo, float hi) {
    f32x2 r; asm("mov.b64 %0, {%1, %2};" : "=l"(r) : "f"(lo), "f"(hi)); return r;
}
__device__ __forceinline__ void upk(float& lo, float& hi, f32x2 v) {
    asm("mov.b64 {%0, %1}, %2;" : "=f"(lo), "=f"(hi) : "l"(v));
}
__device__ __forceinline__ f32x2 sub2(f32x2 a, f32x2 b) {
    f32x2 r; asm("sub.rn.f32x2 %0, %1, %2;" : "=l"(r) : "l"(a), "l"(b)); return r;
}
__device__ __forceinline__ f32x2 mul2(f32x2 a, f32x2 b) {
    f32x2 r; asm("mul.rn.f32x2 %0, %1, %2;" : "=l"(r) : "l"(a), "l"(b)); return r;
}
__device__ __forceinline__ f32x2 fma2(f32x2 a, f32x2 b, f32x2 c) {
    f32x2 r; asm("fma.rn.f32x2 %0, %1, %2, %3;" : "=l"(r) : "l"(a), "l"(b), "l"(c)); return r;
}
__device__ __forceinline__ float rsqrt_approx(float x) {
    float r; asm("rsqrt.approx.f32 %0, %1;" : "=f"(r) : "f"(x)); return r;
}

__global__ __launch_bounds__(THREADS, 2)
void rvo_kernel(const float2* __restrict__ p_cur,
                const float2* __restrict__ v_cur,
                const float2* __restrict__ v_desire,
                const int*    __restrict__ near_idx,
                const float*  __restrict__ neigh_mask,
                const int*    __restrict__ thr_ptr,
                float2*       __restrict__ out)
{
    __shared__ float4 pv[NPED];       // {p.x,p.y,v.x,v.y} whole batch, 16 KB
    __shared__ float2 vds[THREADS];   // v_desire for this block's peds, 4 KB

    const int b       = blockIdx.x / BPB;
    const int sub     = blockIdx.x % BPB;
    const int base    = b * NPED;
    const int pedbase = sub * THREADS;

    #pragma unroll
    for (int i = threadIdx.x; i < NPED; i += THREADS) {
        const float2 p = p_cur[base + i];
        const float2 v = v_cur[base + i];
        pv[i] = make_float4(p.x, p.y, v.x, v.y);
    }
    vds[threadIdx.x] = v_desire[base + pedbase + threadIdx.x];
    __syncthreads();

    const int warp = threadIdx.x >> 5;
    const int lane = threadIdx.x & 31;
    const int grp  = lane >> 3;            // ped (0..3) within a pass
    const int q8   = lane & 7;

    const float thrF = (float)(*thr_ptr);
    const float thr2 = thrF * thrF;
    const f32x2 eps2 = pk(2e-6f, 2e-6f);   // ref: (+1e-6)+1e-6 folded

    const int nb = pedbase + warp * 32;    // within-batch id of warp's first ped
    const int g0 = base + nb;

    const int4*   idx4 = (const int4*)  (near_idx)   + (long long)g0 * (KNEI / 4) + lane;
    const float4* msk4 = (const float4*)(neigh_mask) + (long long)g0 * (KNEI / 4) + lane;

    // Prologue: pass 0's loads.
    int4   j4 = idx4[0];
    float4 m4 = msk4[0];

    // Persistent gather registers (predicated loads keep stale finite values;
    // the m==0 collision test below discards any garbage math).
    float4 q0 = make_float4(0.f, 0.f, 0.f, 0.f);
    float4 q1 = make_float4(0.f, 0.f, 0.f, 0.f);

    #pragma unroll 1
    for (int c = 0; c < 8; ++c) {
        int4 jn; float4 mn;
        if (c < 7) { jn = idx4[(c + 1) * 32]; mn = msk4[(c + 1) * 32]; }

        const int pl = c * 4 + grp;
        const float4 sf = pv[nb + pl];
        const float2 vd = vds[warp * 32 + pl];

        // Per-pass packed broadcasts of self state.
        const f32x2 sfx2 = pk(sf.x, sf.x);
        const f32x2 sfy2 = pk(sf.y, sf.y);
        const f32x2 vdx2 = pk(vd.x, vd.x);
        const f32x2 vdy2 = pk(vd.y, vd.y);

        const int   js[4] = { j4.x, j4.y, j4.z, j4.w };
        const float ms[4] = { m4.x, m4.y, m4.z, m4.w };

        f32x2 accX = 0ull, accY = 0ull;    // packed partials over neighbor pairs

        #pragma unroll
        for (int up = 0; up < 2; ++up) {
            const float mm0 = ms[2 * up];
            const float mm1 = ms[2 * up + 1];
            // Predicated gathers (exactly as R11): m==0 lanes skip the LDS.
            if (mm0 != 0.0f) q0 = pv[js[2 * up]];
            if (mm1 != 0.0f) q1 = pv[js[2 * up + 1]];

            // Transpose gathered components into neighbor-pair lanes.
            const f32x2 qx2 = pk(q0.x, q1.x);
            const f32x2 qy2 = pk(q0.y, q1.y);
            const f32x2 qz2 = pk(q0.z, q1.z);
            const f32x2 qw2 = pk(q0.w, q1.w);

            const f32x2 rpx2 = sub2(sfx2, qx2);
            const f32x2 rpy2 = sub2(sfy2, qy2);
            const f32x2 rvx2 = sub2(vdx2, qz2);
            const f32x2 rvy2 = sub2(vdy2, qw2);

            const f32x2 dpv2 = fma2(rpx2, rvx2, mul2(rpy2, rvy2));
            const f32x2 dvv2 = fma2(rvx2, rvx2, fma2(rvy2, rvy2, eps2));

            float dp0, dp1, dv0, dv1;
            upk(dp0, dp1, dpv2);
            upk(dv0, dv1, dvv2);
            float t0 = __fdividef(dp0, dv0);
            float t1 = __fdividef(dp1, dv1);
            t0 = fminf(fmaxf(t0, 0.0f), TAU);
            t1 = fminf(fmaxf(t1, 0.0f), TAU);
            const f32x2 t2 = pk(t0, t1);

            const f32x2 dx2  = fma2(t2, rvx2, rpx2);
            const f32x2 dy2  = fma2(t2, rvy2, rpy2);
            const f32x2 md2_2 = fma2(dx2, dx2, mul2(dy2, dy2));   // min_dist^2
            const f32x2 s2    = fma2(rpx2, rpx2, mul2(rpy2, rpy2)); // |rel_pos|^2

            float md0, md1, s0, s1;
            upk(md0, md1, md2_2);
            upk(s0, s1, s2);

            // m in {0,1}: thr2*m==0 -> md2<0 never true -> contrib 0 (ref).
            // s==0 (self, m==1): rp==0 -> contrib 0 * finite = 0 (ref).
            const float inv0 = (md0 < thr2 * mm0) ? rsqrt_approx(fmaxf(s0, 1e-30f)) : 0.0f;
            const float inv1 = (md1 < thr2 * mm1) ? rsqrt_approx(fmaxf(s1, 1e-30f)) : 0.0f;
            const f32x2 inv2 = pk(inv0, inv1);

            accX = fma2(rpx2, inv2, accX);   // Σ rpx·inv (per neighbor pair)
            accY = fma2(rpy2, inv2, accY);   // Σ rpy·inv
        }

        // Collapse packed partials; cx = -Σ rpy·inv, cy = +Σ rpx·inv.
        float ax0, ax1, ay0, ay1;
        upk(ax0, ax1, accX);
        upk(ay0, ay1, accY);
        float cx = -ay0 - ay1;
        float cy =  ax0 + ax1;

        // Reduce across the 8 lanes sharing this pedestrian.
        #pragma unroll
        for (int o = 1; o < 8; o <<= 1) {
            cx += __shfl_xor_sync(0xffffffffu, cx, o);
            cy += __shfl_xor_sync(0xffffffffu, cy, o);
        }

        if (q8 == 0) {
            out[g0 + pl] = make_float2(vd.x + cx * FIX, vd.y + cy * FIX);
        }

        j4 = jn;
        m4 = mn;
    }
}

extern "C" void kernel_launch(void* const* d_in, const int* in_sizes, int n_in,
                              void* d_out, int out_size)
{
    const float2* p_cur    = (const float2*)d_in[0];
    const float2* v_cur    = (const float2*)d_in[1];
    const float2* v_desire = (const float2*)d_in[2];
    const int*    near_idx = (const int*)d_in[3];
    const float*  mask     = (const float*)d_in[4];
    const int*    thr      = (const int*)d_in[5];
    float2*       out      = (float2*)d_out;

    const int P = in_sizes[0] / 2;          // B*N pedestrians
    const int nBatches = P / NPED;          // 256
    const int blocks = nBatches * BPB;      // 512

    rvo_kernel<<<blocks, THREADS>>>(p_cur, v_cur, v_desire, near_idx, mask, thr, out);
}